// round 5
// baseline (speedup 1.0000x reference)
#include <cuda_runtime.h>

// PointPillarScatter: out[b,c,yi,xi] = feat[b,c,n*] where n* = max point index
// mapping to cell (yi,xi) in batch b (JAX scatter-set last-wins); 0 elsewhere.
// Index math replicates XLA: /0.16f -> *fp32(1/0.16f) == *6.25f exactly.
//
// Structure (R3 + ILP): init -> min(x,y) -> winner atomicMax
//   -> channel-interleave transpose feat[B,C,N] -> feat4[g][n][4]  (16B rows)
//   -> fill: per thread 8 independent 16B gathers + coalesced 32B stores/plane.

namespace {
constexpr int B  = 4;
constexpr int C  = 64;
constexpr int N  = 100000;
constexpr int NY = 496;
constexpr int NX = 432;
constexpr int CELLS  = NY * NX;      // 214272
constexpr int VCELLS = CELLS / 4;    // 53568 (float4 granularity)
constexpr int HV     = VCELLS / 2;   // 26784 (2 cell-quads per thread)
constexpr int G      = B * (C / 4);  // 64 channel-quad groups
constexpr int NV     = N / 4;        // 25000 point-quads
constexpr int HP     = NV / 2;       // 12500 (2 point-quads per thread)
}

// Scratch (no runtime allocation allowed).
__device__ __align__(16) int   g_winner[B * CELLS];
__device__ float g_minxy[B][2];
__device__ __align__(16) float g_feat4[(size_t)G * N * 4];   // 102.4 MB interleaved

__device__ __forceinline__ void atomicMinF(float* addr, float v) {
    if (v >= 0.0f) atomicMin((int*)addr, __float_as_int(v));
    else           atomicMax((unsigned int*)addr, __float_as_uint(v));
}

__global__ void pp_init() {
    int i = blockIdx.x * blockDim.x + threadIdx.x;
    if (i < B * VCELLS) reinterpret_cast<int4*>(g_winner)[i] = make_int4(-1, -1, -1, -1);
    if (i < B * 2) reinterpret_cast<float*>(g_minxy)[i] = __int_as_float(0x7f800000);
}

// Per-batch min over x,y. points row = [b, x, y, z] as float4.
__global__ void pp_min(const float4* __restrict__ pts) {
    const int b = blockIdx.y;
    const float INF = __int_as_float(0x7f800000);
    float mx = INF, my = INF;
    for (int n = blockIdx.x * blockDim.x + threadIdx.x; n < N; n += gridDim.x * blockDim.x) {
        float4 v = pts[b * N + n];
        mx = fminf(mx, v.y);
        my = fminf(my, v.z);
    }
    #pragma unroll
    for (int o = 16; o; o >>= 1) {
        mx = fminf(mx, __shfl_xor_sync(0xffffffffu, mx, o));
        my = fminf(my, __shfl_xor_sync(0xffffffffu, my, o));
    }
    __shared__ float sx[32], sy[32];
    const int warp = threadIdx.x >> 5, lane = threadIdx.x & 31;
    if (lane == 0) { sx[warp] = mx; sy[warp] = my; }
    __syncthreads();
    if (warp == 0) {
        const int nw = blockDim.x >> 5;
        mx = (lane < nw) ? sx[lane] : INF;
        my = (lane < nw) ? sy[lane] : INF;
        #pragma unroll
        for (int o = 16; o; o >>= 1) {
            mx = fminf(mx, __shfl_xor_sync(0xffffffffu, mx, o));
            my = fminf(my, __shfl_xor_sync(0xffffffffu, my, o));
        }
        if (lane == 0) {
            atomicMinF(&g_minxy[b][0], mx);
            atomicMinF(&g_minxy[b][1], my);
        }
    }
}

// Elect per-cell winner = max point index (JAX scatter-set last-wins).
__global__ void pp_winner(const float4* __restrict__ pts) {
    const int b = blockIdx.y;
    const float xmin = g_minxy[b][0];
    const float ymin = g_minxy[b][1];
    const int n = blockIdx.x * blockDim.x + threadIdx.x;
    if (n >= N) return;
    float4 v = pts[b * N + n];
    const float R = 6.25f;                 // fp32(1/0.16f) == 6.25f (XLA rewrite)
    int xi = (int)floorf((v.y - xmin) * R);
    int yi = (int)floorf((v.z - ymin) * R);
    xi = min(max(xi, 0), NX - 1);
    yi = min(max(yi, 0), NY - 1);
    atomicMax(&g_winner[b * CELLS + yi * NX + xi], n);
}

// Channel-interleave transpose: feat[b][c][n] -> feat4[g][n][k], g = b*16 + c/4,
// k = c%4. 8 independent strided loads + 128B contiguous writes per thread.
__global__ void __launch_bounds__(256) pp_transpose(const float* __restrict__ feat) {
    int idx = blockIdx.x * blockDim.x + threadIdx.x;    // over G * HP
    if (idx >= G * HP) return;
    const int p = idx % HP;
    const int g = idx / HP;                             // b*16 + c4
    const float4* base = reinterpret_cast<const float4*>(feat);
    const size_t row = (size_t)g * 4 * NV;
    float4 r0[2], r1[2], r2[2], r3[2];
    #pragma unroll
    for (int j = 0; j < 2; ++j) {
        r0[j] = base[row + 0 * NV + 2 * p + j];
        r1[j] = base[row + 1 * NV + 2 * p + j];
        r2[j] = base[row + 2 * NV + 2 * p + j];
        r3[j] = base[row + 3 * NV + 2 * p + j];
    }
    float4* o = reinterpret_cast<float4*>(g_feat4) + (size_t)g * N + (size_t)p * 8;
    #pragma unroll
    for (int j = 0; j < 2; ++j) {
        o[4 * j + 0] = make_float4(r0[j].x, r1[j].x, r2[j].x, r3[j].x);
        o[4 * j + 1] = make_float4(r0[j].y, r1[j].y, r2[j].y, r3[j].y);
        o[4 * j + 2] = make_float4(r0[j].z, r1[j].z, r2[j].z, r3[j].z);
        o[4 * j + 3] = make_float4(r0[j].w, r1[j].w, r2[j].w, r3[j].w);
    }
}

// Fill: per thread = (group g, 8 cells). 8 independent 16B gathers; 4 planes
// each get a 32B coalesced store.
__global__ void __launch_bounds__(256) pp_fill4(float4* __restrict__ out) {
    const int total = G * HV;
    int idx = blockIdx.x * blockDim.x + threadIdx.x;
    if (idx >= total) return;
    const int h = idx % HV;
    const int g = idx / HV;                             // b*16 + c4
    const int b = g >> 4;
    const int v = 2 * h;
    const int4* wp = reinterpret_cast<const int4*>(g_winner) + b * VCELLS + v;
    int4 w0 = wp[0];
    int4 w1 = wp[1];
    const float4* fp = reinterpret_cast<const float4*>(g_feat4) + (size_t)g * N;
    const float4 z = make_float4(0.f, 0.f, 0.f, 0.f);
    float4 a0 = (w0.x >= 0) ? __ldg(fp + w0.x) : z;
    float4 a1 = (w0.y >= 0) ? __ldg(fp + w0.y) : z;
    float4 a2 = (w0.z >= 0) ? __ldg(fp + w0.z) : z;
    float4 a3 = (w0.w >= 0) ? __ldg(fp + w0.w) : z;
    float4 b0 = (w1.x >= 0) ? __ldg(fp + w1.x) : z;
    float4 b1 = (w1.y >= 0) ? __ldg(fp + w1.y) : z;
    float4 b2 = (w1.z >= 0) ? __ldg(fp + w1.z) : z;
    float4 b3 = (w1.w >= 0) ? __ldg(fp + w1.w) : z;
    float4* ob = out + (size_t)g * 4 * VCELLS + v;
    ob[0 * VCELLS + 0] = make_float4(a0.x, a1.x, a2.x, a3.x);
    ob[0 * VCELLS + 1] = make_float4(b0.x, b1.x, b2.x, b3.x);
    ob[1 * VCELLS + 0] = make_float4(a0.y, a1.y, a2.y, a3.y);
    ob[1 * VCELLS + 1] = make_float4(b0.y, b1.y, b2.y, b3.y);
    ob[2 * VCELLS + 0] = make_float4(a0.z, a1.z, a2.z, a3.z);
    ob[2 * VCELLS + 1] = make_float4(b0.z, b1.z, b2.z, b3.z);
    ob[3 * VCELLS + 0] = make_float4(a0.w, a1.w, a2.w, a3.w);
    ob[3 * VCELLS + 1] = make_float4(b0.w, b1.w, b2.w, b3.w);
}

extern "C" void kernel_launch(void* const* d_in, const int* in_sizes, int n_in,
                              void* d_out, int out_size) {
    (void)in_sizes; (void)n_in; (void)out_size;
    const float*  feat = (const float*)d_in[0];   // (B, C, N) f32
    const float4* pts  = (const float4*)d_in[1];  // (B*N, 4)  f32
    // d_in[2] (voxel_coords) unused by the reference computation.

    pp_init<<<(B * VCELLS + 255) / 256, 256>>>();
    pp_min<<<dim3(98, B), 256>>>(pts);
    pp_winner<<<dim3((N + 255) / 256, B), 256>>>(pts);
    pp_transpose<<<(G * HP + 255) / 256, 256>>>(feat);
    pp_fill4<<<(G * HV + 255) / 256, 256>>>((float4*)d_out);
}

// round 6
// speedup vs baseline: 1.2994x; 1.2994x over previous
#include <cuda_runtime.h>

// PointPillarScatter: out[b,c,yi,xi] = feat[b,c,n*] where n* = max point index
// mapping to cell (yi,xi) in batch b (JAX scatter-set last-wins); 0 elsewhere.
// Index math replicates XLA: /0.16f -> *fp32(1/0.16f) == *6.25f exactly.
//
// R3 structure + split-halves ILP (lane-consecutive addressing preserved):
//   init -> min(x,y) -> winner atomicMax
//   -> channel-interleave transpose feat[B,C,N] -> feat4[g][n][4] (16B rows)
//   -> fill: per thread 2 far-apart cell-quads -> 8 independent 16B gathers,
//      all winner loads / output stores fully coalesced.

namespace {
constexpr int B  = 4;
constexpr int C  = 64;
constexpr int N  = 100000;
constexpr int NY = 496;
constexpr int NX = 432;
constexpr int CELLS  = NY * NX;      // 214272
constexpr int VCELLS = CELLS / 4;    // 53568 (float4 granularity)
constexpr int HV     = VCELLS / 2;   // 26784  (split-half stride, cells)
constexpr int G      = B * (C / 4);  // 64 channel-quad groups
constexpr int NV     = N / 4;        // 25000 point-quads
constexpr int HP     = NV / 2;       // 12500  (split-half stride, points)
}

// Scratch (no runtime allocation allowed).
__device__ __align__(16) int   g_winner[B * CELLS];
__device__ float g_minxy[B][2];
__device__ __align__(16) float g_feat4[(size_t)G * N * 4];   // 102.4 MB interleaved

__device__ __forceinline__ void atomicMinF(float* addr, float v) {
    if (v >= 0.0f) atomicMin((int*)addr, __float_as_int(v));
    else           atomicMax((unsigned int*)addr, __float_as_uint(v));
}

__global__ void pp_init() {
    int i = blockIdx.x * blockDim.x + threadIdx.x;
    if (i < B * VCELLS) reinterpret_cast<int4*>(g_winner)[i] = make_int4(-1, -1, -1, -1);
    if (i < B * 2) reinterpret_cast<float*>(g_minxy)[i] = __int_as_float(0x7f800000);
}

// Per-batch min over x,y. points row = [b, x, y, z] as float4.
__global__ void pp_min(const float4* __restrict__ pts) {
    const int b = blockIdx.y;
    const float INF = __int_as_float(0x7f800000);
    float mx = INF, my = INF;
    for (int n = blockIdx.x * blockDim.x + threadIdx.x; n < N; n += gridDim.x * blockDim.x) {
        float4 v = pts[b * N + n];
        mx = fminf(mx, v.y);
        my = fminf(my, v.z);
    }
    #pragma unroll
    for (int o = 16; o; o >>= 1) {
        mx = fminf(mx, __shfl_xor_sync(0xffffffffu, mx, o));
        my = fminf(my, __shfl_xor_sync(0xffffffffu, my, o));
    }
    __shared__ float sx[32], sy[32];
    const int warp = threadIdx.x >> 5, lane = threadIdx.x & 31;
    if (lane == 0) { sx[warp] = mx; sy[warp] = my; }
    __syncthreads();
    if (warp == 0) {
        const int nw = blockDim.x >> 5;
        mx = (lane < nw) ? sx[lane] : INF;
        my = (lane < nw) ? sy[lane] : INF;
        #pragma unroll
        for (int o = 16; o; o >>= 1) {
            mx = fminf(mx, __shfl_xor_sync(0xffffffffu, mx, o));
            my = fminf(my, __shfl_xor_sync(0xffffffffu, my, o));
        }
        if (lane == 0) {
            atomicMinF(&g_minxy[b][0], mx);
            atomicMinF(&g_minxy[b][1], my);
        }
    }
}

// Elect per-cell winner = max point index (JAX scatter-set last-wins).
__global__ void pp_winner(const float4* __restrict__ pts) {
    const int b = blockIdx.y;
    const float xmin = g_minxy[b][0];
    const float ymin = g_minxy[b][1];
    const int n = blockIdx.x * blockDim.x + threadIdx.x;
    if (n >= N) return;
    float4 v = pts[b * N + n];
    const float R = 6.25f;                 // fp32(1/0.16f) == 6.25f (XLA rewrite)
    int xi = (int)floorf((v.y - xmin) * R);
    int yi = (int)floorf((v.z - ymin) * R);
    xi = min(max(xi, 0), NX - 1);
    yi = min(max(yi, 0), NY - 1);
    atomicMax(&g_winner[b * CELLS + yi * NX + xi], n);
}

// Channel-interleave transpose: feat[b][c][n] -> feat4[g][n][k], g = b*16+c/4,
// k = c%4. Split-halves ILP: thread handles point-quads p and p+HP; every
// request is lane-consecutive (fully coalesced), 8 loads in flight.
__global__ void __launch_bounds__(256) pp_transpose(const float* __restrict__ feat) {
    int idx = blockIdx.x * blockDim.x + threadIdx.x;    // over G * HP
    if (idx >= G * HP) return;
    const int p = idx % HP;
    const int g = idx / HP;                             // b*16 + c4
    const float4* base = reinterpret_cast<const float4*>(feat);
    const size_t row = (size_t)g * 4 * NV;
    float4 r0[2], r1[2], r2[2], r3[2];
    #pragma unroll
    for (int j = 0; j < 2; ++j) {
        const int nv = p + j * HP;
        r0[j] = base[row + 0 * NV + nv];
        r1[j] = base[row + 1 * NV + nv];
        r2[j] = base[row + 2 * NV + nv];
        r3[j] = base[row + 3 * NV + nv];
    }
    float4* o = reinterpret_cast<float4*>(g_feat4) + (size_t)g * N;
    #pragma unroll
    for (int j = 0; j < 2; ++j) {
        const int nv = p + j * HP;
        o[nv * 4 + 0] = make_float4(r0[j].x, r1[j].x, r2[j].x, r3[j].x);
        o[nv * 4 + 1] = make_float4(r0[j].y, r1[j].y, r2[j].y, r3[j].y);
        o[nv * 4 + 2] = make_float4(r0[j].z, r1[j].z, r2[j].z, r3[j].z);
        o[nv * 4 + 3] = make_float4(r0[j].w, r1[j].w, r2[j].w, r3[j].w);
    }
}

// Fill: per thread = (group g, cell-quads h and h+HV). 8 independent 16B
// gathers in flight; winner loads and output stores fully coalesced.
__global__ void __launch_bounds__(256) pp_fill4(float4* __restrict__ out) {
    const int total = G * HV;
    int idx = blockIdx.x * blockDim.x + threadIdx.x;
    if (idx >= total) return;
    const int h = idx % HV;
    const int g = idx / HV;                             // b*16 + c4
    const int b = g >> 4;
    const int4* wp = reinterpret_cast<const int4*>(g_winner) + b * VCELLS;
    int4 w0 = wp[h];
    int4 w1 = wp[h + HV];
    const float4* fp = reinterpret_cast<const float4*>(g_feat4) + (size_t)g * N;
    const float4 z = make_float4(0.f, 0.f, 0.f, 0.f);
    float4 a0 = (w0.x >= 0) ? __ldg(fp + w0.x) : z;
    float4 a1 = (w0.y >= 0) ? __ldg(fp + w0.y) : z;
    float4 a2 = (w0.z >= 0) ? __ldg(fp + w0.z) : z;
    float4 a3 = (w0.w >= 0) ? __ldg(fp + w0.w) : z;
    float4 b0 = (w1.x >= 0) ? __ldg(fp + w1.x) : z;
    float4 b1 = (w1.y >= 0) ? __ldg(fp + w1.y) : z;
    float4 b2 = (w1.z >= 0) ? __ldg(fp + w1.z) : z;
    float4 b3 = (w1.w >= 0) ? __ldg(fp + w1.w) : z;
    float4* ob = out + (size_t)g * 4 * VCELLS;
    ob[0 * VCELLS + h]      = make_float4(a0.x, a1.x, a2.x, a3.x);
    ob[1 * VCELLS + h]      = make_float4(a0.y, a1.y, a2.y, a3.y);
    ob[2 * VCELLS + h]      = make_float4(a0.z, a1.z, a2.z, a3.z);
    ob[3 * VCELLS + h]      = make_float4(a0.w, a1.w, a2.w, a3.w);
    ob[0 * VCELLS + h + HV] = make_float4(b0.x, b1.x, b2.x, b3.x);
    ob[1 * VCELLS + h + HV] = make_float4(b0.y, b1.y, b2.y, b3.y);
    ob[2 * VCELLS + h + HV] = make_float4(b0.z, b1.z, b2.z, b3.z);
    ob[3 * VCELLS + h + HV] = make_float4(b0.w, b1.w, b2.w, b3.w);
}

extern "C" void kernel_launch(void* const* d_in, const int* in_sizes, int n_in,
                              void* d_out, int out_size) {
    (void)in_sizes; (void)n_in; (void)out_size;
    const float*  feat = (const float*)d_in[0];   // (B, C, N) f32
    const float4* pts  = (const float4*)d_in[1];  // (B*N, 4)  f32
    // d_in[2] (voxel_coords) unused by the reference computation.

    pp_init<<<(B * VCELLS + 255) / 256, 256>>>();
    pp_min<<<dim3(98, B), 256>>>(pts);
    pp_winner<<<dim3((N + 255) / 256, B), 256>>>(pts);
    pp_transpose<<<(G * HP + 255) / 256, 256>>>(feat);
    pp_fill4<<<(G * HV + 255) / 256, 256>>>((float4*)d_out);
}